// round 16
// baseline (speedup 1.0000x reference)
#include <cuda_runtime.h>
#include <cuda_fp16.h>
#include <cstdint>

#define B_  4
#define S_  2048
#define D_  1024
#define H_  16
#define DH_ 64
#define M_  (B_*S_)   // 8192

// ---------------- scratch (static __device__, no allocation) ----------------
__device__ __half g_Q [(size_t)M_*D_];   // [B,H,S,DH]
__device__ __half g_K [(size_t)M_*D_];
__device__ __half g_V [(size_t)M_*D_];
__device__ __half g_AO[(size_t)M_*D_];   // [B*S, D] merged heads
__device__ __half g_xh[(size_t)M_*D_];
__device__ __half g_Wh[4][(size_t)D_*D_];

// ---------------------------------------------------------------------------
__device__ __forceinline__ uint32_t pack2h(float x, float y) {
    __half2 v(__float2half_rn(x), __float2half_rn(y));
    return *(uint32_t*)&v;
}

// ---------------------------------------------------------------------------
// fused conversion: x (2M float4) + 4 weights -> single fp16.
// Grid-stride, ~8 elements per thread -> deeper MLP.
// ---------------------------------------------------------------------------
#define NX4 ((M_*D_)/4)     // 2M
#define NW4 ((D_*D_)/4)     // 256K
#define NTOT (NX4 + 4*NW4)  // 3M

__global__ __launch_bounds__(256) void cvt_all(const float4* __restrict__ x,
                                               const float4* __restrict__ w0,
                                               const float4* __restrict__ w1,
                                               const float4* __restrict__ w2,
                                               const float4* __restrict__ w3) {
    const int stride = gridDim.x * blockDim.x;
    for (int i = blockIdx.x * blockDim.x + threadIdx.x; i < NTOT; i += stride) {
        const float4* src;
        uint32_t* dst;
        int idx;
        if (i < NX4) {
            src = x; idx = i;
            dst = (uint32_t*)g_xh;
        } else {
            int j = i - NX4;
            int w = j / NW4;
            idx = j - w * NW4;
            src = (w == 0) ? w0 : (w == 1) ? w1 : (w == 2) ? w2 : w3;
            dst = (uint32_t*)(g_Wh[0] + (size_t)w * D_ * D_);
        }
        float4 v = src[idx];
        dst[2*idx]   = pack2h(v.x, v.y);
        dst[2*idx+1] = pack2h(v.z, v.w);
    }
}

// ---------------------------------------------------------------------------
// common PTX macros
// ---------------------------------------------------------------------------
#define CP16(dst, src) \
    asm volatile("cp.async.cg.shared.global [%0], [%1], 16;\n" :: "r"(dst), "l"(src))
#define CP_COMMIT() asm volatile("cp.async.commit_group;\n" ::: "memory")
#define CP_WAIT(n)  asm volatile("cp.async.wait_group %0;\n" :: "n"(n) : "memory")

#define LDM_X4(r0,r1,r2,r3, addr) \
    asm volatile("ldmatrix.sync.aligned.m8n8.x4.shared.b16 {%0,%1,%2,%3}, [%4];" \
                 : "=r"(r0),"=r"(r1),"=r"(r2),"=r"(r3) : "r"(addr))
#define LDM_X4T(r0,r1,r2,r3, addr) \
    asm volatile("ldmatrix.sync.aligned.m8n8.x4.trans.shared.b16 {%0,%1,%2,%3}, [%4];" \
                 : "=r"(r0),"=r"(r1),"=r"(r2),"=r"(r3) : "r"(addr))

#define MMA16816(c0,c1,c2,c3, a0,a1,a2,a3, b0,b1) \
    asm volatile("mma.sync.aligned.m16n8k16.row.col.f32.f16.f16.f32 " \
                 "{%0,%1,%2,%3}, {%4,%5,%6,%7}, {%8,%9}, {%0,%1,%2,%3};" \
                 : "+f"(c0),"+f"(c1),"+f"(c2),"+f"(c3) \
                 : "r"(a0),"r"(a1),"r"(a2),"r"(a3),"r"(b0),"r"(b1))

// ---------------------------------------------------------------------------
// single-fp16 GEMM (R15 measured-best, unchanged):
// C[m,n] = sum_k A[m,k]*W[n,k] + bias[n]
// 128x128 CTA tile, BK=64, 3-stage cp.async ring, ONE barrier per k-step,
// prefetch burst after first slab, A+B via ldmatrix.x4, float2 O-epilogue.
// ---------------------------------------------------------------------------
#define BM 128
#define BN 128
#define GBK 64
#define LDW 72                    // fp16 per smem row (144 B = 9 x 16B, odd)
#define GTILE (128*LDW*2)         // 18432 B
#define GSTAGE (2*GTILE)          // 36864 B: A, W
#define GNST   3
#define GSMEM  (GNST*GSTAGE)      // 110592 B
#define GITERS (D_/GBK)           // 16

#define STAGE_LOAD(st, kb) do {                                                   \
    _Pragma("unroll")                                                             \
    for (int i_ = 0; i_ < 8; i_++) {                                              \
        int c_ = tid + (i_ << 8);                                                 \
        int t_ = c_ >> 10;                                                        \
        int r_ = (c_ >> 3) & 127;                                                 \
        int c8_ = c_ & 7;                                                         \
        uint32_t dst_ = smBase + (uint32_t)((st) * GSTAGE + t_ * GTILE            \
                                            + r_ * (LDW*2) + c8_ * 16);           \
        const __half* s_ = t_ ? Wp : Ap;                                          \
        size_t g_ = (size_t)((t_ ? nBase : mBase) + r_) * D_ + (kb) + c8_ * 8;    \
        CP16(dst_, s_ + g_);                                                      \
    }                                                                             \
    CP_COMMIT();                                                                  \
} while (0)

#define GEMM_KK(k0v) do {                                                         \
    const int k0 = (k0v);                                                         \
    uint32_t af[4][4], b4[2][4];                                                  \
    _Pragma("unroll")                                                             \
    for (int mi = 0; mi < 4; mi++) {                                              \
        int row = wm * 64 + mi * 16 + aRow;                                       \
        uint32_t off = stBase + (uint32_t)(row * LDW + k0 + aK) * 2;              \
        LDM_X4(af[mi][0], af[mi][1], af[mi][2], af[mi][3], off);                  \
    }                                                                             \
    _Pragma("unroll")                                                             \
    for (int ni2 = 0; ni2 < 2; ni2++) {                                           \
        int row = wn * 32 + ni2 * 16 + bRow16;                                    \
        uint32_t off = stBase + GTILE + (uint32_t)(row * LDW + k0 + bK4) * 2;     \
        LDM_X4(b4[ni2][0], b4[ni2][1], b4[ni2][2], b4[ni2][3], off);              \
    }                                                                             \
    _Pragma("unroll")                                                             \
    for (int mi = 0; mi < 4; mi++)                                                \
        _Pragma("unroll")                                                         \
        for (int ni = 0; ni < 4; ni++) {                                          \
            int ni2 = ni >> 1, par = ni & 1;                                      \
            MMA16816(c[mi][ni][0], c[mi][ni][1], c[mi][ni][2], c[mi][ni][3],      \
                     af[mi][0], af[mi][1], af[mi][2], af[mi][3],                  \
                     b4[ni2][par ? 1 : 0], b4[ni2][par ? 3 : 2]);                 \
        }                                                                         \
} while (0)

extern "C" __global__ __launch_bounds__(256, 2) void gemm_f16(
    const __half* __restrict__ Ap, const __half* __restrict__ WB,
    const float* __restrict__ b0p, const float* __restrict__ b1p,
    const float* __restrict__ b2p, float* __restrict__ outp, int mode_base)
{
    extern __shared__ __half sm[];
    const int zi = blockIdx.z;
    const int mode = mode_base ? 3 : zi;
    const __half* Wp = WB + (size_t)zi * D_ * D_;
    const float* bias = (zi == 0) ? b0p : (zi == 1) ? b1p : b2p;

    const int tid  = threadIdx.x;
    const int wid  = tid >> 5, lane = tid & 31;
    const int wm   = wid >> 2, wn = wid & 3;
    const int mBase = blockIdx.y * BM;
    const int nBase = blockIdx.x * BN;
    const uint32_t smBase = (uint32_t)__cvta_generic_to_shared(sm);

    float c[4][4][4];
    #pragma unroll
    for (int mi = 0; mi < 4; mi++)
        #pragma unroll
        for (int ni = 0; ni < 4; ni++)
            #pragma unroll
            for (int e = 0; e < 4; e++) c[mi][ni][e] = 0.f;

    const int aRow  = lane & 15;
    const int aK    = (lane >> 4) * 8;
    const int bRow16 = lane & 15;
    const int bK4    = (lane >> 4) * 8;

    STAGE_LOAD(0, 0);
    STAGE_LOAD(1, GBK);

    for (int kt = 0; kt < GITERS; kt++) {
        CP_WAIT(1);
        __syncthreads();

        const uint32_t stBase = smBase + (uint32_t)((kt % GNST) * GSTAGE);

        GEMM_KK(0);

        if (kt + 2 < GITERS) {
            STAGE_LOAD((kt + 2) % GNST, (kt + 2) * GBK);
        } else {
            CP_COMMIT();
        }

        GEMM_KK(16);
        GEMM_KK(32);
        GEMM_KK(48);
    }

    // ---------------- epilogue ----------------
    const int g  = lane >> 2;
    const int th = lane & 3;

    if (mode == 3) {
        #pragma unroll
        for (int mi = 0; mi < 4; mi++)
            #pragma unroll
            for (int ni = 0; ni < 4; ni++) {
                int row0 = mBase + wm * 64 + mi * 16 + g;
                int col0 = nBase + wn * 32 + ni * 8 + th * 2;
                float b0v = bias[col0], b1v = bias[col0 + 1];
                float2 v0 = make_float2(c[mi][ni][0] + b0v, c[mi][ni][1] + b1v);
                float2 v1 = make_float2(c[mi][ni][2] + b0v, c[mi][ni][3] + b1v);
                *(float2*)&outp[(size_t)row0 * D_ + col0]       = v0;
                *(float2*)&outp[(size_t)(row0 + 8) * D_ + col0] = v1;
            }
    } else {
        __half* dst = (mode == 0) ? g_Q : (mode == 1) ? g_K : g_V;
        #pragma unroll
        for (int mi = 0; mi < 4; mi++)
            #pragma unroll
            for (int ni = 0; ni < 4; ni++) {
                int row0 = mBase + wm * 64 + mi * 16 + g;
                int col0 = nBase + wn * 32 + ni * 8 + th * 2;
                float b0v = bias[col0], b1v = bias[col0 + 1];
                int hh = col0 >> 6, dh = col0 & 63;
                #pragma unroll
                for (int pr = 0; pr < 2; pr++) {
                    int m = row0 + pr * 8;
                    int b = m >> 11, s = m & 2047;
                    float v0 = c[mi][ni][pr*2]   + b0v;
                    float v1 = c[mi][ni][pr*2+1] + b1v;
                    size_t idx = (((size_t)(b * H_ + hh)) * S_ + s) * DH_ + dh;
                    *(uint32_t*)&dst[idx] = pack2h(v0, v1);
                }
            }
    }
}

// ---------------------------------------------------------------------------
// Tensor-core flash attention (causal), single fp16.
// BQ=128, 8 warps, 3-stage K/V pipeline, one barrier per tile, coarse
// per-warp causal skip, LPT CTA order, __launch_bounds__(256,2).
// NEW: Q staged into ring buffer 2 concurrently with K/V tiles 0-1
// (prologue DMAs overlap; pre-loop barrier removed — kt=0 barrier orders
// Q-frag pulls before buffer 2's first reuse at the kt+2 prefetch).
// ---------------------------------------------------------------------------
#define LDF 72
#define FTILEB (64*LDF*2)      // 9216 B per 64-row tile
#define FSTAGE (2*FTILEB)      // 18432 B: K, V  (== Q tile size)
#define FNST   3
#define FSMEM  (FNST*FSTAGE)   // 55296 B dynamic

__global__ __launch_bounds__(256, 2) void flash_tc() {
    extern __shared__ __half fsm[];
    const uint32_t smBase = (uint32_t)__cvta_generic_to_shared(fsm);

    const int bh = blockIdx.y;
    const int Qb = (int)gridDim.x - 1 - (int)blockIdx.x;   // LPT: big first
    const int q0 = Qb * 128;
    const int tid  = threadIdx.x;
    const int wq   = tid >> 5, lane = tid & 31;
    const int g    = lane >> 2, th = lane & 3;

    const size_t base = (size_t)bh * S_ * DH_;
    const __half* Qp = g_Q + base;
    const __half* Kp = g_K + base;
    const __half* Vp = g_V + base;

    const int NT = 2 * Qb + 2;

#define FLOAD(st, ktv) do {                                                       \
    _Pragma("unroll")                                                             \
    for (int i_ = 0; i_ < 4; i_++) {                                              \
        int c_ = tid + i_ * 256;                                                  \
        int t_ = c_ >> 9, r_ = (c_ >> 3) & 63, c8_ = c_ & 7;                      \
        const __half* s_ = t_ ? Vp : Kp;                                          \
        CP16(smBase + (uint32_t)((st) * FSTAGE + t_ * FTILEB                      \
                                 + r_ * (LDF*2) + c8_ * 16),                      \
             s_ + (size_t)((ktv) * 64 + r_) * DH_ + c8_ * 8);                     \
    }                                                                             \
    CP_COMMIT();                                                                  \
} while (0)

    // ---- prologue: Q -> buffer 2, then tiles 0 and 1 (all DMAs overlap) ----
    const uint32_t qBase = smBase + 2u * FSTAGE;
    #pragma unroll
    for (int i = 0; i < 4; i++) {
        int c = tid + i * 256;
        int r = (c >> 3) & 127, c8 = c & 7;
        CP16(qBase + (uint32_t)(r * (LDF*2) + c8 * 16),
             Qp + (size_t)(q0 + r) * DH_ + c8 * 8);
    }
    CP_COMMIT();          // group: Q
    FLOAD(0, 0);          // group: tile 0
    FLOAD(1, 1);          // group: tile 1   (NT >= 2 always)

    CP_WAIT(2);           // Q landed; tiles 0/1 may still be in flight
    __syncthreads();      // Q visible to all warps

    uint32_t qf[4][4];
    {
        const int aRow = lane & 15, aK = (lane >> 4) * 8;
        int row = wq * 16 + aRow;
        #pragma unroll
        for (int j = 0; j < 4; j++) {
            uint32_t off = qBase + (uint32_t)(row * LDF + j * 16 + aK) * 2;
            LDM_X4(qf[j][0], qf[j][1], qf[j][2], qf[j][3], off);
        }
    }
    // no extra barrier: the kt=0 top-of-loop __syncthreads orders all Q-frag
    // pulls before buffer 2's first overwrite (the kt+2 prefetch below).

    float m0 = -1e30f, m1 = -1e30f, l0 = 0.f, l1 = 0.f;
    float co[8][4];
    #pragma unroll
    for (int nt = 0; nt < 8; nt++)
        #pragma unroll
        for (int e = 0; e < 4; e++) co[nt][e] = 0.f;

    const int r16 = lane & 15;            // x4 row index
    const int k8  = (lane >> 4) * 8;      // x4 column offset
    const int wmaxq = q0 + wq * 16 + 15;

    for (int kt = 0; kt < NT; kt++) {
        CP_WAIT(1);            // tile kt landed
        __syncthreads();       // all warps past compute of kt-1 (and Q pulls)

        if (kt + 2 < NT) {
            FLOAD((kt + 2) % 3, kt + 2);
        } else {
            CP_COMMIT();
        }

        if (kt * 64 <= wmaxq) {
            const uint32_t smK = smBase + (uint32_t)((kt % 3) * FSTAGE);
            const uint32_t smV = smK + FTILEB;

            // ---- S = Q K^T, j-outer, K via x4 ----
            float cs[8][4];
            #pragma unroll
            for (int nt = 0; nt < 8; nt++)
                #pragma unroll
                for (int e = 0; e < 4; e++) cs[nt][e] = 0.f;

            #pragma unroll
            for (int j = 0; j < 4; j++) {
                uint32_t k4[4][4];
                #pragma unroll
                for (int ntp = 0; ntp < 4; ntp++) {
                    uint32_t off = smK +
                        (uint32_t)((ntp*16 + r16) * LDF + j*16 + k8) * 2;
                    LDM_X4(k4[ntp][0], k4[ntp][1], k4[ntp][2], k4[ntp][3], off);
                }
                // non-trans map: even nt {r0,r2}, odd nt {r1,r3}
                #pragma unroll
                for (int nt = 0; nt < 8; nt++) {
                    int ntp = nt >> 1, par = nt & 1;
                    MMA16816(cs[nt][0], cs[nt][1], cs[nt][2], cs[nt][3],
                             qf[j][0], qf[j][1], qf[j][2], qf[j][3],
                             k4[ntp][par ? 1 : 0], k4[ntp][par ? 3 : 2]);
                }
            }

            const float scale = 0.125f;
            if (kt * 64 + 63 > q0 + wq * 16) {
                #pragma unroll
                for (int nt = 0; nt < 8; nt++) {
                    int kn = kt * 64 + nt * 8 + th * 2;
                    #pragma unroll
                    for (int e = 0; e < 4; e++) {
                        int kidx = kn + (e & 1);
                        int qi   = q0 + wq * 16 + g + (e >> 1) * 8;
                        cs[nt][e] = (kidx <= qi) ? cs[nt][e] * scale : -1e30f;
                    }
                }
            } else {
                #pragma unroll
                for (int nt = 0; nt < 8; nt++)
                    #pragma unroll
                    for (int e = 0; e < 4; e++) cs[nt][e] *= scale;
            }

            float tm0 = -1e30f, tm1 = -1e30f;
            #pragma unroll
            for (int nt = 0; nt < 8; nt++) {
                tm0 = fmaxf(tm0, fmaxf(cs[nt][0], cs[nt][1]));
                tm1 = fmaxf(tm1, fmaxf(cs[nt][2], cs[nt][3]));
            }
            tm0 = fmaxf(tm0, __shfl_xor_sync(0xffffffffu, tm0, 1));
            tm0 = fmaxf(tm0, __shfl_xor_sync(0xffffffffu, tm0, 2));
            tm1 = fmaxf(tm1, __shfl_xor_sync(0xffffffffu, tm1, 1));
            tm1 = fmaxf(tm1, __shfl_xor_sync(0xffffffffu, tm1, 2));

            float mn0 = fmaxf(m0, tm0), mn1 = fmaxf(m1, tm1);
            float cr0 = __expf(m0 - mn0), cr1 = __expf(m1 - mn1);
            m0 = mn0; m1 = mn1;
            l0 *= cr0; l1 *= cr1;
            #pragma unroll
            for (int nt = 0; nt < 8; nt++) {
                co[nt][0] *= cr0; co[nt][1] *= cr0;
                co[nt][2] *= cr1; co[nt][3] *= cr1;
            }

            uint32_t pf[4][4];
            #pragma unroll
            for (int nt = 0; nt < 8; nt++) {
                float p0 = __expf(cs[nt][0] - m0);
                float p1 = __expf(cs[nt][1] - m0);
                float p2 = __expf(cs[nt][2] - m1);
                float p3 = __expf(cs[nt][3] - m1);
                l0 += p0 + p1;
                l1 += p2 + p3;
                int j = nt >> 1, hh = (nt & 1) * 2;
                pf[j][hh]     = pack2h(p0, p1);   // row g,   keys k..k+1
                pf[j][hh + 1] = pack2h(p2, p3);   // row g+8, keys k..k+1
            }

            // ---- O += P V, j-outer, V via x4.trans ----
            #pragma unroll
            for (int j = 0; j < 4; j++) {
                uint32_t v4[4][4];
                #pragma unroll
                for (int ntp = 0; ntp < 4; ntp++) {
                    uint32_t off = smV +
                        (uint32_t)((j*16 + r16) * LDF + ntp*16 + k8) * 2;
                    LDM_X4T(v4[ntp][0], v4[ntp][1], v4[ntp][2], v4[ntp][3], off);
                }
                // trans map: even nt {r0,r1}, odd nt {r2,r3}
                #pragma unroll
                for (int nt = 0; nt < 8; nt++) {
                    int ntp = nt >> 1, par = nt & 1;
                    MMA16816(co[nt][0], co[nt][1], co[nt][2], co[nt][3],
                             pf[j][0], pf[j][1], pf[j][2], pf[j][3],
                             v4[ntp][par ? 2 : 0], v4[ntp][par ? 3 : 1]);
                }
            }
        }
    }

    l0 += __shfl_xor_sync(0xffffffffu, l0, 1);
    l0 += __shfl_xor_sync(0xffffffffu, l0, 2);
    l1 += __shfl_xor_sync(0xffffffffu, l1, 1);
    l1 += __shfl_xor_sync(0xffffffffu, l1, 2);
    float inv0 = 1.f / l0, inv1 = 1.f / l1;

    const int b  = bh >> 4, hh = bh & 15;
    const int r0 = q0 + wq * 16 + g;
    #pragma unroll
    for (int nt = 0; nt < 8; nt++) {
        int dh = nt * 8 + th * 2;
        size_t i0 = ((size_t)(b * S_ + r0))     * D_ + hh * DH_ + dh;
        size_t i1 = ((size_t)(b * S_ + r0 + 8)) * D_ + hh * DH_ + dh;
        *(uint32_t*)&g_AO[i0] = pack2h(co[nt][0] * inv0, co[nt][1] * inv0);
        *(uint32_t*)&g_AO[i1] = pack2h(co[nt][2] * inv1, co[nt][3] * inv1);
    }
#undef FLOAD
}

// ---------------------------------------------------------------------------
extern "C" void kernel_launch(void* const* d_in, const int* in_sizes, int n_in,
                              void* d_out, int out_size) {
    const float* x  = (const float*)d_in[0];
    const float* Wq = (const float*)d_in[1];
    const float* bq = (const float*)d_in[2];
    const float* Wk = (const float*)d_in[3];
    const float* bk = (const float*)d_in[4];
    const float* Wv = (const float*)d_in[5];
    const float* bv = (const float*)d_in[6];
    const float* Wo = (const float*)d_in[7];
    const float* bo = (const float*)d_in[8];
    float* out = (float*)d_out;

    cudaFuncSetAttribute(gemm_f16, cudaFuncAttributeMaxDynamicSharedMemorySize,
                         GSMEM);
    cudaFuncSetAttribute(flash_tc, cudaFuncAttributeMaxDynamicSharedMemorySize,
                         FSMEM);

    __half *xh, *ao, *wh;
    cudaGetSymbolAddress((void**)&xh, g_xh);
    cudaGetSymbolAddress((void**)&ao, g_AO);
    cudaGetSymbolAddress((void**)&wh, g_Wh);

    // conversion: ~8 elements per thread (grid-stride)
    cvt_all<<<(NTOT / 8 + 255) / 256, 256>>>((const float4*)x,
        (const float4*)Wq, (const float4*)Wk, (const float4*)Wv, (const float4*)Wo);

    // fused QKV projection (gridDim.z = 3)
    dim3 gq(D_ / BN, M_ / BM, 3);
    gemm_f16<<<gq, 256, GSMEM>>>(xh, wh, bq, bk, bv, nullptr, 0);

    dim3 fg(S_ / 128, B_ * H_);  // (16, 64)
    flash_tc<<<fg, 256, FSMEM>>>();

    // O projection
    dim3 go(D_ / BN, M_ / BM, 1);
    gemm_f16<<<go, 256, GSMEM>>>(ao, wh + 3 * (size_t)D_ * D_,
                                 bo, bo, bo, out, 3);
}

// round 17
// speedup vs baseline: 1.0025x; 1.0025x over previous
#include <cuda_runtime.h>
#include <cuda_fp16.h>
#include <cstdint>

#define B_  4
#define S_  2048
#define D_  1024
#define H_  16
#define DH_ 64
#define M_  (B_*S_)   // 8192

// ---------------- scratch (static __device__, no allocation) ----------------
__device__ __half g_Q [(size_t)M_*D_];   // [B,H,S,DH]
__device__ __half g_K [(size_t)M_*D_];
__device__ __half g_V [(size_t)M_*D_];
__device__ __half g_AO[(size_t)M_*D_];   // [B*S, D] merged heads
__device__ __half g_xh[(size_t)M_*D_];
__device__ __half g_Wh[4][(size_t)D_*D_];

// ---------------------------------------------------------------------------
__device__ __forceinline__ uint32_t pack2h(float x, float y) {
    __half2 v(__float2half_rn(x), __float2half_rn(y));
    return *(uint32_t*)&v;
}

// ---------------------------------------------------------------------------
// fused conversion: x (2M float4) + 4 weights -> single fp16.
// Grid-stride, ~4 elements per thread -> MLP 4.
// ---------------------------------------------------------------------------
#define NX4 ((M_*D_)/4)     // 2M
#define NW4 ((D_*D_)/4)     // 256K
#define NTOT (NX4 + 4*NW4)  // 3M

__global__ __launch_bounds__(256) void cvt_all(const float4* __restrict__ x,
                                               const float4* __restrict__ w0,
                                               const float4* __restrict__ w1,
                                               const float4* __restrict__ w2,
                                               const float4* __restrict__ w3) {
    const int stride = gridDim.x * blockDim.x;
    for (int i = blockIdx.x * blockDim.x + threadIdx.x; i < NTOT; i += stride) {
        const float4* src;
        uint32_t* dst;
        int idx;
        if (i < NX4) {
            src = x; idx = i;
            dst = (uint32_t*)g_xh;
        } else {
            int j = i - NX4;
            int w = j / NW4;
            idx = j - w * NW4;
            src = (w == 0) ? w0 : (w == 1) ? w1 : (w == 2) ? w2 : w3;
            dst = (uint32_t*)(g_Wh[0] + (size_t)w * D_ * D_);
        }
        float4 v = src[idx];
        dst[2*idx]   = pack2h(v.x, v.y);
        dst[2*idx+1] = pack2h(v.z, v.w);
    }
}

// ---------------------------------------------------------------------------
// common PTX macros
// ---------------------------------------------------------------------------
#define CP16(dst, src) \
    asm volatile("cp.async.cg.shared.global [%0], [%1], 16;\n" :: "r"(dst), "l"(src))
#define CP_COMMIT() asm volatile("cp.async.commit_group;\n" ::: "memory")
#define CP_WAIT(n)  asm volatile("cp.async.wait_group %0;\n" :: "n"(n) : "memory")

#define LDM_X4(r0,r1,r2,r3, addr) \
    asm volatile("ldmatrix.sync.aligned.m8n8.x4.shared.b16 {%0,%1,%2,%3}, [%4];" \
                 : "=r"(r0),"=r"(r1),"=r"(r2),"=r"(r3) : "r"(addr))
#define LDM_X4T(r0,r1,r2,r3, addr) \
    asm volatile("ldmatrix.sync.aligned.m8n8.x4.trans.shared.b16 {%0,%1,%2,%3}, [%4];" \
                 : "=r"(r0),"=r"(r1),"=r"(r2),"=r"(r3) : "r"(addr))

#define MMA16816(c0,c1,c2,c3, a0,a1,a2,a3, b0,b1) \
    asm volatile("mma.sync.aligned.m16n8k16.row.col.f32.f16.f16.f32 " \
                 "{%0,%1,%2,%3}, {%4,%5,%6,%7}, {%8,%9}, {%0,%1,%2,%3};" \
                 : "+f"(c0),"+f"(c1),"+f"(c2),"+f"(c3) \
                 : "r"(a0),"r"(a1),"r"(a2),"r"(a3),"r"(b0),"r"(b1))

// ---------------------------------------------------------------------------
// single-fp16 GEMM:  C[m,n] = sum_k A[m,k]*W[n,k] + bias[n]
// 128x128 CTA tile, BK=64, 3-stage cp.async ring, ONE barrier per k-step,
// prefetch burst after first slab, A+B via ldmatrix.x4, float2 O-epilogue.
// ---------------------------------------------------------------------------
#define BM 128
#define BN 128
#define GBK 64
#define LDW 72                    // fp16 per smem row (144 B = 9 x 16B, odd)
#define GTILE (128*LDW*2)         // 18432 B
#define GSTAGE (2*GTILE)          // 36864 B: A, W
#define GNST   3
#define GSMEM  (GNST*GSTAGE)      // 110592 B
#define GITERS (D_/GBK)           // 16

#define STAGE_LOAD(st, kb) do {                                                   \
    _Pragma("unroll")                                                             \
    for (int i_ = 0; i_ < 8; i_++) {                                              \
        int c_ = tid + (i_ << 8);                                                 \
        int t_ = c_ >> 10;                                                        \
        int r_ = (c_ >> 3) & 127;                                                 \
        int c8_ = c_ & 7;                                                         \
        uint32_t dst_ = smBase + (uint32_t)((st) * GSTAGE + t_ * GTILE            \
                                            + r_ * (LDW*2) + c8_ * 16);           \
        const __half* s_ = t_ ? Wp : Ap;                                          \
        size_t g_ = (size_t)((t_ ? nBase : mBase) + r_) * D_ + (kb) + c8_ * 8;    \
        CP16(dst_, s_ + g_);                                                      \
    }                                                                             \
    CP_COMMIT();                                                                  \
} while (0)

#define GEMM_KK(k0v) do {                                                         \
    const int k0 = (k0v);                                                         \
    uint32_t af[4][4], b4[2][4];                                                  \
    _Pragma("unroll")                                                             \
    for (int mi = 0; mi < 4; mi++) {                                              \
        int row = wm * 64 + mi * 16 + aRow;                                       \
        uint32_t off = stBase + (uint32_t)(row * LDW + k0 + aK) * 2;              \
        LDM_X4(af[mi][0], af[mi][1], af[mi][2], af[mi][3], off);                  \
    }                                                                             \
    _Pragma("unroll")                                                             \
    for (int ni2 = 0; ni2 < 2; ni2++) {                                           \
        int row = wn * 32 + ni2 * 16 + bRow16;                                    \
        uint32_t off = stBase + GTILE + (uint32_t)(row * LDW + k0 + bK4) * 2;     \
        LDM_X4(b4[ni2][0], b4[ni2][1], b4[ni2][2], b4[ni2][3], off);              \
    }                                                                             \
    _Pragma("unroll")                                                             \
    for (int mi = 0; mi < 4; mi++)                                                \
        _Pragma("unroll")                                                         \
        for (int ni = 0; ni < 4; ni++) {                                          \
            int ni2 = ni >> 1, par = ni & 1;                                      \
            MMA16816(c[mi][ni][0], c[mi][ni][1], c[mi][ni][2], c[mi][ni][3],      \
                     af[mi][0], af[mi][1], af[mi][2], af[mi][3],                  \
                     b4[ni2][par ? 1 : 0], b4[ni2][par ? 3 : 2]);                 \
        }                                                                         \
} while (0)

extern "C" __global__ __launch_bounds__(256, 2) void gemm_f16(
    const __half* __restrict__ Ap, const __half* __restrict__ WB,
    const float* __restrict__ b0p, const float* __restrict__ b1p,
    const float* __restrict__ b2p, float* __restrict__ outp, int mode_base)
{
    extern __shared__ __half sm[];
    const int zi = blockIdx.z;
    const int mode = mode_base ? 3 : zi;
    const __half* Wp = WB + (size_t)zi * D_ * D_;
    const float* bias = (zi == 0) ? b0p : (zi == 1) ? b1p : b2p;

    const int tid  = threadIdx.x;
    const int wid  = tid >> 5, lane = tid & 31;
    const int wm   = wid >> 2, wn = wid & 3;
    const int mBase = blockIdx.y * BM;
    const int nBase = blockIdx.x * BN;
    const uint32_t smBase = (uint32_t)__cvta_generic_to_shared(sm);

    float c[4][4][4];
    #pragma unroll
    for (int mi = 0; mi < 4; mi++)
        #pragma unroll
        for (int ni = 0; ni < 4; ni++)
            #pragma unroll
            for (int e = 0; e < 4; e++) c[mi][ni][e] = 0.f;

    const int aRow  = lane & 15;
    const int aK    = (lane >> 4) * 8;
    const int bRow16 = lane & 15;
    const int bK4    = (lane >> 4) * 8;

    STAGE_LOAD(0, 0);
    STAGE_LOAD(1, GBK);

    for (int kt = 0; kt < GITERS; kt++) {
        CP_WAIT(1);
        __syncthreads();

        const uint32_t stBase = smBase + (uint32_t)((kt % GNST) * GSTAGE);

        GEMM_KK(0);

        if (kt + 2 < GITERS) {
            STAGE_LOAD((kt + 2) % GNST, (kt + 2) * GBK);
        } else {
            CP_COMMIT();
        }

        GEMM_KK(16);
        GEMM_KK(32);
        GEMM_KK(48);
    }

    // ---------------- epilogue ----------------
    const int g  = lane >> 2;
    const int th = lane & 3;

    if (mode == 3) {
        #pragma unroll
        for (int mi = 0; mi < 4; mi++)
            #pragma unroll
            for (int ni = 0; ni < 4; ni++) {
                int row0 = mBase + wm * 64 + mi * 16 + g;
                int col0 = nBase + wn * 32 + ni * 8 + th * 2;
                float b0v = bias[col0], b1v = bias[col0 + 1];
                float2 v0 = make_float2(c[mi][ni][0] + b0v, c[mi][ni][1] + b1v);
                float2 v1 = make_float2(c[mi][ni][2] + b0v, c[mi][ni][3] + b1v);
                *(float2*)&outp[(size_t)row0 * D_ + col0]       = v0;
                *(float2*)&outp[(size_t)(row0 + 8) * D_ + col0] = v1;
            }
    } else {
        __half* dst = (mode == 0) ? g_Q : (mode == 1) ? g_K : g_V;
        #pragma unroll
        for (int mi = 0; mi < 4; mi++)
            #pragma unroll
            for (int ni = 0; ni < 4; ni++) {
                int row0 = mBase + wm * 64 + mi * 16 + g;
                int col0 = nBase + wn * 32 + ni * 8 + th * 2;
                float b0v = bias[col0], b1v = bias[col0 + 1];
                int hh = col0 >> 6, dh = col0 & 63;
                #pragma unroll
                for (int pr = 0; pr < 2; pr++) {
                    int m = row0 + pr * 8;
                    int b = m >> 11, s = m & 2047;
                    float v0 = c[mi][ni][pr*2]   + b0v;
                    float v1 = c[mi][ni][pr*2+1] + b1v;
                    size_t idx = (((size_t)(b * H_ + hh)) * S_ + s) * DH_ + dh;
                    *(uint32_t*)&dst[idx] = pack2h(v0, v1);
                }
            }
    }
}

// ---------------------------------------------------------------------------
// Tensor-core flash attention (causal), single fp16 — measured-best (R12/R14).
// BQ=128, 8 warps, 3-stage K/V pipeline, one barrier per tile, coarse
// per-warp causal skip only, LPT CTA order, __launch_bounds__(256,2).
// K via x4 (non-trans), V via x4.trans.
// ---------------------------------------------------------------------------
#define LDF 72
#define FTILEB (64*LDF*2)      // 9216 B per 64-row tile
#define FSTAGE (2*FTILEB)      // 18432 B: K, V
#define FNST   3
#define FSMEM  (FNST*FSTAGE)   // 55296 B dynamic

__global__ __launch_bounds__(256, 2) void flash_tc() {
    extern __shared__ __half fsm[];
    const uint32_t smBase = (uint32_t)__cvta_generic_to_shared(fsm);

    const int bh = blockIdx.y;
    const int Qb = (int)gridDim.x - 1 - (int)blockIdx.x;   // LPT: big first
    const int q0 = Qb * 128;
    const int tid  = threadIdx.x;
    const int wq   = tid >> 5, lane = tid & 31;
    const int g    = lane >> 2, th = lane & 3;

    const size_t base = (size_t)bh * S_ * DH_;
    const __half* Qp = g_Q + base;
    const __half* Kp = g_K + base;
    const __half* Vp = g_V + base;

    // ---- stage Q (18432 B) into buffer 0, pull frags ----
    #pragma unroll
    for (int i = 0; i < 4; i++) {
        int c = tid + i * 256;
        int r = (c >> 3) & 127, c8 = c & 7;
        CP16(smBase + (uint32_t)(r * (LDF*2) + c8 * 16),
             Qp + (size_t)(q0 + r) * DH_ + c8 * 8);
    }
    CP_COMMIT();
    CP_WAIT(0);
    __syncthreads();

    uint32_t qf[4][4];
    {
        const int aRow = lane & 15, aK = (lane >> 4) * 8;
        int row = wq * 16 + aRow;
        #pragma unroll
        for (int j = 0; j < 4; j++) {
            uint32_t off = smBase + (uint32_t)(row * LDF + j * 16 + aK) * 2;
            LDM_X4(qf[j][0], qf[j][1], qf[j][2], qf[j][3], off);
        }
    }
    __syncthreads();   // Q frags read before tile loads overwrite buffer 0

    float m0 = -1e30f, m1 = -1e30f, l0 = 0.f, l1 = 0.f;
    float co[8][4];
    #pragma unroll
    for (int nt = 0; nt < 8; nt++)
        #pragma unroll
        for (int e = 0; e < 4; e++) co[nt][e] = 0.f;

    const int r16 = lane & 15;            // x4 row index
    const int k8  = (lane >> 4) * 8;      // x4 column offset
    const int wmaxq = q0 + wq * 16 + 15;

    const int NT = 2 * Qb + 2;

#define FLOAD(st, ktv) do {                                                       \
    _Pragma("unroll")                                                             \
    for (int i_ = 0; i_ < 4; i_++) {                                              \
        int c_ = tid + i_ * 256;                                                  \
        int t_ = c_ >> 9, r_ = (c_ >> 3) & 63, c8_ = c_ & 7;                      \
        const __half* s_ = t_ ? Vp : Kp;                                          \
        CP16(smBase + (uint32_t)((st) * FSTAGE + t_ * FTILEB                      \
                                 + r_ * (LDF*2) + c8_ * 16),                      \
             s_ + (size_t)((ktv) * 64 + r_) * DH_ + c8_ * 8);                     \
    }                                                                             \
    CP_COMMIT();                                                                  \
} while (0)

    // prologue: 2 tiles in flight
    FLOAD(0, 0);
    FLOAD(1, 1);   // NT >= 2 always

    for (int kt = 0; kt < NT; kt++) {
        CP_WAIT(1);            // tile kt landed
        __syncthreads();       // all warps past compute of kt-1

        if (kt + 2 < NT) {
            FLOAD((kt + 2) % 3, kt + 2);
        } else {
            CP_COMMIT();
        }

        if (kt * 64 <= wmaxq) {
            const uint32_t smK = smBase + (uint32_t)((kt % 3) * FSTAGE);
            const uint32_t smV = smK + FTILEB;

            // ---- S = Q K^T, j-outer, K via x4 ----
            float cs[8][4];
            #pragma unroll
            for (int nt = 0; nt < 8; nt++)
                #pragma unroll
                for (int e = 0; e < 4; e++) cs[nt][e] = 0.f;

            #pragma unroll
            for (int j = 0; j < 4; j++) {
                uint32_t k4[4][4];
                #pragma unroll
                for (int ntp = 0; ntp < 4; ntp++) {
                    uint32_t off = smK +
                        (uint32_t)((ntp*16 + r16) * LDF + j*16 + k8) * 2;
                    LDM_X4(k4[ntp][0], k4[ntp][1], k4[ntp][2], k4[ntp][3], off);
                }
                // non-trans map: even nt {r0,r2}, odd nt {r1,r3}
                #pragma unroll
                for (int nt = 0; nt < 8; nt++) {
                    int ntp = nt >> 1, par = nt & 1;
                    MMA16816(cs[nt][0], cs[nt][1], cs[nt][2], cs[nt][3],
                             qf[j][0], qf[j][1], qf[j][2], qf[j][3],
                             k4[ntp][par ? 1 : 0], k4[ntp][par ? 3 : 2]);
                }
            }

            const float scale = 0.125f;
            if (kt * 64 + 63 > q0 + wq * 16) {
                #pragma unroll
                for (int nt = 0; nt < 8; nt++) {
                    int kn = kt * 64 + nt * 8 + th * 2;
                    #pragma unroll
                    for (int e = 0; e < 4; e++) {
                        int kidx = kn + (e & 1);
                        int qi   = q0 + wq * 16 + g + (e >> 1) * 8;
                        cs[nt][e] = (kidx <= qi) ? cs[nt][e] * scale : -1e30f;
                    }
                }
            } else {
                #pragma unroll
                for (int nt = 0; nt < 8; nt++)
                    #pragma unroll
                    for (int e = 0; e < 4; e++) cs[nt][e] *= scale;
            }

            float tm0 = -1e30f, tm1 = -1e30f;
            #pragma unroll
            for (int nt = 0; nt < 8; nt++) {
                tm0 = fmaxf(tm0, fmaxf(cs[nt][0], cs[nt][1]));
                tm1 = fmaxf(tm1, fmaxf(cs[nt][2], cs[nt][3]));
            }
            tm0 = fmaxf(tm0, __shfl_xor_sync(0xffffffffu, tm0, 1));
            tm0 = fmaxf(tm0, __shfl_xor_sync(0xffffffffu, tm0, 2));
            tm1 = fmaxf(tm1, __shfl_xor_sync(0xffffffffu, tm1, 1));
            tm1 = fmaxf(tm1, __shfl_xor_sync(0xffffffffu, tm1, 2));

            float mn0 = fmaxf(m0, tm0), mn1 = fmaxf(m1, tm1);
            float cr0 = __expf(m0 - mn0), cr1 = __expf(m1 - mn1);
            m0 = mn0; m1 = mn1;
            l0 *= cr0; l1 *= cr1;
            #pragma unroll
            for (int nt = 0; nt < 8; nt++) {
                co[nt][0] *= cr0; co[nt][1] *= cr0;
                co[nt][2] *= cr1; co[nt][3] *= cr1;
            }

            uint32_t pf[4][4];
            #pragma unroll
            for (int nt = 0; nt < 8; nt++) {
                float p0 = __expf(cs[nt][0] - m0);
                float p1 = __expf(cs[nt][1] - m0);
                float p2 = __expf(cs[nt][2] - m1);
                float p3 = __expf(cs[nt][3] - m1);
                l0 += p0 + p1;
                l1 += p2 + p3;
                int j = nt >> 1, hh = (nt & 1) * 2;
                pf[j][hh]     = pack2h(p0, p1);   // row g,   keys k..k+1
                pf[j][hh + 1] = pack2h(p2, p3);   // row g+8, keys k..k+1
            }

            // ---- O += P V, j-outer, V via x4.trans ----
            #pragma unroll
            for (int j = 0; j < 4; j++) {
                uint32_t v4[4][4];
                #pragma unroll
                for (int ntp = 0; ntp < 4; ntp++) {
                    uint32_t off = smV +
                        (uint32_t)((j*16 + r16) * LDF + ntp*16 + k8) * 2;
                    LDM_X4T(v4[ntp][0], v4[ntp][1], v4[ntp][2], v4[ntp][3], off);
                }
                // trans map: even nt {r0,r1}, odd nt {r2,r3}
                #pragma unroll
                for (int nt = 0; nt < 8; nt++) {
                    int ntp = nt >> 1, par = nt & 1;
                    MMA16816(co[nt][0], co[nt][1], co[nt][2], co[nt][3],
                             pf[j][0], pf[j][1], pf[j][2], pf[j][3],
                             v4[ntp][par ? 2 : 0], v4[ntp][par ? 3 : 1]);
                }
            }
        }
    }

    l0 += __shfl_xor_sync(0xffffffffu, l0, 1);
    l0 += __shfl_xor_sync(0xffffffffu, l0, 2);
    l1 += __shfl_xor_sync(0xffffffffu, l1, 1);
    l1 += __shfl_xor_sync(0xffffffffu, l1, 2);
    float inv0 = 1.f / l0, inv1 = 1.f / l1;

    const int b  = bh >> 4, hh = bh & 15;
    const int r0 = q0 + wq * 16 + g;
    #pragma unroll
    for (int nt = 0; nt < 8; nt++) {
        int dh = nt * 8 + th * 2;
        size_t i0 = ((size_t)(b * S_ + r0))     * D_ + hh * DH_ + dh;
        size_t i1 = ((size_t)(b * S_ + r0 + 8)) * D_ + hh * DH_ + dh;
        *(uint32_t*)&g_AO[i0] = pack2h(co[nt][0] * inv0, co[nt][1] * inv0);
        *(uint32_t*)&g_AO[i1] = pack2h(co[nt][2] * inv1, co[nt][3] * inv1);
    }
#undef FLOAD
}

// ---------------------------------------------------------------------------
extern "C" void kernel_launch(void* const* d_in, const int* in_sizes, int n_in,
                              void* d_out, int out_size) {
    const float* x  = (const float*)d_in[0];
    const float* Wq = (const float*)d_in[1];
    const float* bq = (const float*)d_in[2];
    const float* Wk = (const float*)d_in[3];
    const float* bk = (const float*)d_in[4];
    const float* Wv = (const float*)d_in[5];
    const float* bv = (const float*)d_in[6];
    const float* Wo = (const float*)d_in[7];
    const float* bo = (const float*)d_in[8];
    float* out = (float*)d_out;

    cudaFuncSetAttribute(gemm_f16, cudaFuncAttributeMaxDynamicSharedMemorySize,
                         GSMEM);
    cudaFuncSetAttribute(flash_tc, cudaFuncAttributeMaxDynamicSharedMemorySize,
                         FSMEM);

    __half *xh, *ao, *wh;
    cudaGetSymbolAddress((void**)&xh, g_xh);
    cudaGetSymbolAddress((void**)&ao, g_AO);
    cudaGetSymbolAddress((void**)&wh, g_Wh);

    // conversion: ~4 elements per thread (grid-stride)
    cvt_all<<<(NTOT / 4 + 255) / 256, 256>>>((const float4*)x,
        (const float4*)Wq, (const float4*)Wk, (const float4*)Wv, (const float4*)Wo);

    // fused QKV projection (gridDim.z = 3)
    dim3 gq(D_ / BN, M_ / BM, 3);
    gemm_f16<<<gq, 256, GSMEM>>>(xh, wh, bq, bk, bv, nullptr, 0);

    dim3 fg(S_ / 128, B_ * H_);  // (16, 64)
    flash_tc<<<fg, 256, FSMEM>>>();

    // O projection
    dim3 go(D_ / BN, M_ / BM, 1);
    gemm_f16<<<go, 256, GSMEM>>>(ao, wh + 3 * (size_t)D_ * D_,
                                 bo, bo, bo, out, 3);
}